// round 6
// baseline (speedup 1.0000x reference)
#include <cuda_runtime.h>
#include <stdint.h>

#define NROW 16384
#define KC 64
#define NCHUNK (NROW / KC)            /* 256 */
#define STG 3
#define HALF_STAGE 32768u             /* A (or B) per stage: 128 x 64 fp32 */
#define STAGE_BYTES 65536u
#define BIG_SMEM (STG * STAGE_BYTES)  /* 196608 */
#define PREP_SMEM ((64 * 64 + 128 * 132) * 4)

__device__ float g_Tt[128 * NROW];    /* B operand, K-major, tf32-rounded */
__device__ float g_X[NROW * 128];     /* layer activations */

__device__ __forceinline__ float eluf(float x) { return x > 0.f ? x : expm1f(x); }
__device__ __forceinline__ uint32_t swz(uint32_t x) { return x ^ ((x >> 3) & 0x70); }

__device__ __forceinline__ uint32_t smem_u32(const void* p) {
    uint32_t a;
    asm("{ .reg .u64 t; cvta.to.shared.u64 t, %1; cvt.u32.u64 %0, t; }" : "=r"(a) : "l"(p));
    return a;
}
__device__ __forceinline__ void cp_async16(uint32_t dst, const void* src) {
    asm volatile("cp.async.cg.shared.global [%0], [%1], 16;" :: "r"(dst), "l"(src) : "memory");
}
__device__ __forceinline__ void ldsm_x4(uint32_t* r, uint32_t addr) {
    asm volatile("ldmatrix.sync.aligned.m8n8.x4.shared.b16 {%0,%1,%2,%3}, [%4];"
                 : "=r"(r[0]), "=r"(r[1]), "=r"(r[2]), "=r"(r[3]) : "r"(addr));
}
__device__ __forceinline__ void mma_tf32(float* c, const uint32_t* a, const uint32_t* b) {
    asm volatile(
        "mma.sync.aligned.m16n8k8.row.col.f32.tf32.tf32.f32 "
        "{%0,%1,%2,%3}, {%4,%5,%6,%7}, {%8,%9}, {%0,%1,%2,%3};"
        : "+f"(c[0]), "+f"(c[1]), "+f"(c[2]), "+f"(c[3])
        : "r"(a[0]), "r"(a[1]), "r"(a[2]), "r"(a[3]), "r"(b[0]), "r"(b[1]));
}
__device__ __forceinline__ float tf32r(float x) {
    uint32_t u;
    asm("cvt.rna.tf32.f32 %0, %1;" : "=r"(u) : "f"(x));
    return __uint_as_float(u);
}

/* Tt[j][k] = sum_d f(src[k][d(+64)]) * W[d][j&63]; output tf32-rounded */
__global__ __launch_bounds__(512) void gcn_prep(const float* __restrict__ Xin,
                                                const float* __restrict__ W,
                                                int apply_elu, int use_gx) {
    extern __shared__ float sm[];
    float* sW = sm;
    float* sXT = sm + 64 * 64;
    const float* src = use_gx ? (const float*)g_X : Xin;
    int tid = threadIdx.x;
    int k0 = blockIdx.x * 128;

    for (int l = tid; l < 64 * 64; l += 512) sW[l] = W[l];
    #pragma unroll
    for (int it = 0; it < 32; ++it) {
        int l = it * 512 + tid;
        int k = l >> 7, d = l & 127;
        float v = src[(size_t)(k0 + k) * 128 + d];
        if (apply_elu) v = eluf(v);
        sXT[d * 132 + k] = v;
    }
    __syncthreads();

    int warp = tid >> 5, lane = tid & 31;
    int k = lane * 4;
    for (int jp = warp; jp < 64; jp += 16) {
        float4 a0 = make_float4(0.f, 0.f, 0.f, 0.f);
        float4 a1 = make_float4(0.f, 0.f, 0.f, 0.f);
        #pragma unroll 16
        for (int d = 0; d < 64; ++d) {
            float w = sW[d * 64 + jp];
            float4 xs = *(const float4*)&sXT[d * 132 + k];
            float4 xu = *(const float4*)&sXT[(64 + d) * 132 + k];
            a0.x = fmaf(xs.x, w, a0.x); a0.y = fmaf(xs.y, w, a0.y);
            a0.z = fmaf(xs.z, w, a0.z); a0.w = fmaf(xs.w, w, a0.w);
            a1.x = fmaf(xu.x, w, a1.x); a1.y = fmaf(xu.y, w, a1.y);
            a1.z = fmaf(xu.z, w, a1.z); a1.w = fmaf(xu.w, w, a1.w);
        }
        a0.x = tf32r(a0.x); a0.y = tf32r(a0.y); a0.z = tf32r(a0.z); a0.w = tf32r(a0.w);
        a1.x = tf32r(a1.x); a1.y = tf32r(a1.y); a1.z = tf32r(a1.z); a1.w = tf32r(a1.w);
        *(float4*)&g_Tt[(size_t)jp * NROW + k0 + k] = a0;
        *(float4*)&g_Tt[(size_t)(jp + 64) * NROW + k0 + k] = a1;
    }
}

/* g_X[m][n] = elu( sum_k adj[m][k] * Tt[n][k] + bias[n&63] )
   16 warps; warp pair (w, w+8) K-splits one 32x64 output tile. */
__global__ __launch_bounds__(512, 1) void gcn_big(const float* __restrict__ adj,
                                                  const float* __restrict__ bias) {
    extern __shared__ char dsm[];
    uint32_t sb = smem_u32(dsm);
    int tid = threadIdx.x;
    int lane = tid & 31, wid = tid >> 5;
    int w8 = wid & 7;
    int kg = wid >> 3;                    /* K-group: 0 -> k-block 0, 1 -> k-block 1 */
    int wm = w8 & 3, wn = w8 >> 2;        /* warp tile: 32(m) x 64(n) */
    int m0 = blockIdx.x * 128;
    int grp = lane >> 3, li = lane & 7;

    float acc[2][8][4];
    #pragma unroll
    for (int i = 0; i < 2; ++i)
        #pragma unroll
        for (int j = 0; j < 8; ++j)
            #pragma unroll
            for (int r = 0; r < 4; ++r) acc[i][j][r] = 0.f;

    const float* gA = adj + (size_t)m0 * NROW;
    const float* gB = g_Tt;

    /* fragment smem offsets within this warp's 16KB k-block; segs 4..7 via XOR 64 */
    uint32_t kbase = (uint32_t)(kg * 16384);
    uint32_t aOff[2][2], bOff[4][2];
    #pragma unroll
    for (int mi = 0; mi < 2; ++mi) {
        int rowa = wm * 32 + mi * 16 + ((grp & 1) << 3) + li;
        #pragma unroll
        for (int ts = 0; ts < 2; ++ts) {
            int seg = ts * 2 + (grp >> 1);
            aOff[mi][ts] = kbase + swz((uint32_t)(rowa * 128 + seg * 16));
        }
    }
    #pragma unroll
    for (int p = 0; p < 4; ++p) {
        int rowb = wn * 64 + p * 16 + ((grp >> 1) << 3) + li;
        #pragma unroll
        for (int ts = 0; ts < 2; ++ts) {
            int seg = ts * 2 + (grp & 1);
            bOff[p][ts] = kbase + swz((uint32_t)(rowb * 128 + seg * 16));
        }
    }

#define LOAD_STAGE(ii) do {                                                     \
    uint32_t st_ = sb + (uint32_t)((ii) % STG) * STAGE_BYTES;                   \
    int k0_ = (ii) * KC;                                                        \
    _Pragma("unroll")                                                           \
    for (int j_ = 0; j_ < 4; ++j_) {                                            \
        int v_ = j_ * 512 + tid;                                                \
        int blk_ = v_ >> 10;                                                    \
        int row_ = (v_ >> 3) & 127;                                             \
        int seg_ = v_ & 7;                                                      \
        uint32_t off_ = (uint32_t)(blk_ * 16384) +                              \
                        swz((uint32_t)(row_ * 128 + seg_ * 16));                \
        size_t go_ = (size_t)row_ * NROW + k0_ + blk_ * 32 + seg_ * 4;          \
        cp_async16(st_ + off_, gA + go_);                                       \
        cp_async16(st_ + HALF_STAGE + off_, gB + go_);                          \
    }                                                                           \
    asm volatile("cp.async.commit_group;" ::: "memory");                        \
} while (0)

    LOAD_STAGE(0); LOAD_STAGE(1);

    #pragma unroll 1
    for (int i = 0; i < NCHUNK; ++i) {
        asm volatile("cp.async.wait_group 1;" ::: "memory");
        __syncthreads();
        if (i + 2 < NCHUNK) LOAD_STAGE(i + 2);
        else asm volatile("cp.async.commit_group;" ::: "memory");
        uint32_t sA = sb + (uint32_t)(i % STG) * STAGE_BYTES;
        uint32_t sB = sA + HALF_STAGE;
        #pragma unroll
        for (int tt = 0; tt < 4; ++tt) {
            uint32_t hx = (uint32_t)((tt >> 1) * 64);
            int q = tt & 1;
            uint32_t af[2][4], bf[8][2];
            #pragma unroll
            for (int mi = 0; mi < 2; ++mi)
                ldsm_x4(af[mi], sA + (aOff[mi][q] ^ hx));
            #pragma unroll
            for (int mi = 0; mi < 2; ++mi)
                #pragma unroll
                for (int r = 0; r < 4; ++r)
                    asm("cvt.rna.tf32.f32 %0, %0;" : "+r"(af[mi][r]));
            #pragma unroll
            for (int p = 0; p < 4; ++p) {
                uint32_t r4[4];
                ldsm_x4(r4, sB + (bOff[p][q] ^ hx));
                bf[2 * p][0] = r4[0]; bf[2 * p][1] = r4[1];
                bf[2 * p + 1][0] = r4[2]; bf[2 * p + 1][1] = r4[3];
            }
            #pragma unroll
            for (int mi = 0; mi < 2; ++mi)
                #pragma unroll
                for (int ni = 0; ni < 8; ++ni)
                    mma_tf32(acc[mi][ni], af[mi], bf[ni]);
        }
    }
    asm volatile("cp.async.wait_group 0;" ::: "memory");
    __syncthreads();

    /* K-split reduction: kg==1 warps dump accs, kg==0 warps add + epilogue.
       Layout [w8*32+lane][68] floats -> conflict-free float4 (stride 68). */
    float* sred = (float*)dsm;
    if (kg == 1) {
        float* dst = sred + (size_t)(w8 * 32 + lane) * 68;
        #pragma unroll
        for (int mi = 0; mi < 2; ++mi)
            #pragma unroll
            for (int ni = 0; ni < 8; ++ni)
                *(float4*)&dst[mi * 32 + ni * 4] = *(float4*)acc[mi][ni];
    }
    __syncthreads();
    if (kg == 0) {
        const float* src = sred + (size_t)(w8 * 32 + lane) * 68;
        int col0 = wn * 64 + (lane & 3) * 2;
        int rbase = m0 + wm * 32 + (lane >> 2);
        #pragma unroll
        for (int mi = 0; mi < 2; ++mi)
            #pragma unroll
            for (int ni = 0; ni < 8; ++ni) {
                float4 o = *(const float4*)&src[mi * 32 + ni * 4];
                int col = col0 + ni * 8;
                float b0v = bias[col & 63], b1v = bias[(col + 1) & 63];
                int rlo = rbase + mi * 16;
                float2 v0 = make_float2(eluf(acc[mi][ni][0] + o.x + b0v),
                                        eluf(acc[mi][ni][1] + o.y + b1v));
                float2 v1 = make_float2(eluf(acc[mi][ni][2] + o.z + b0v),
                                        eluf(acc[mi][ni][3] + o.w + b1v));
                *(float2*)&g_X[(size_t)rlo * 128 + col] = v0;
                *(float2*)&g_X[(size_t)(rlo + 8) * 128 + col] = v1;
            }
    }
#undef LOAD_STAGE
}

/* out[k][o] = sum_j g_X[k][j] * Wl[o][j] + bl[o] */
__global__ __launch_bounds__(256) void gcn_final(const float* __restrict__ Wl,
                                                 const float* __restrict__ bl,
                                                 float* __restrict__ out) {
    __shared__ float sWlT[128 * 32];
    int tid = threadIdx.x;
    for (int l = tid; l < 4096; l += 256) {
        int o = l >> 7, j = l & 127;
        sWlT[j * 32 + o] = Wl[l];
    }
    __syncthreads();
    int warp = tid >> 5, lane = tid & 31;
    int k0 = blockIdx.x * 128;
    float b = bl[lane];
    for (int r = warp; r < 128; r += 8) {
        const float* yrow = g_X + (size_t)(k0 + r) * 128;
        float acc = b;
        #pragma unroll 16
        for (int j = 0; j < 128; ++j)
            acc = fmaf(__ldg(&yrow[j]), sWlT[j * 32 + lane], acc);
        out[(size_t)(k0 + r) * 32 + lane] = acc;
    }
}

extern "C" void kernel_launch(void* const* d_in, const int* in_sizes, int n_in,
                              void* d_out, int out_size) {
    const float* z   = (const float*)d_in[0];
    const float* adj = (const float*)d_in[1];
    const float* W0  = (const float*)d_in[2];
    const float* b0  = (const float*)d_in[3];
    const float* W1  = (const float*)d_in[4];
    const float* b1  = (const float*)d_in[5];
    const float* Wl  = (const float*)d_in[6];
    const float* bl  = (const float*)d_in[7];
    float* out = (float*)d_out;

    cudaFuncSetAttribute(gcn_prep, cudaFuncAttributeMaxDynamicSharedMemorySize, PREP_SMEM);
    cudaFuncSetAttribute(gcn_big,  cudaFuncAttributeMaxDynamicSharedMemorySize, BIG_SMEM);

    gcn_prep<<<128, 512, PREP_SMEM>>>(z, W0, 1, 0);
    gcn_big <<<128, 512, BIG_SMEM>>>(adj, b0);
    gcn_prep<<<128, 512, PREP_SMEM>>>(z, W1, 0, 1);
    gcn_big <<<128, 512, BIG_SMEM>>>(adj, b1);
    gcn_final<<<128, 256>>>(Wl, bl, out);
}

// round 7
// speedup vs baseline: 1.0991x; 1.0991x over previous
#include <cuda_runtime.h>
#include <cuda_fp16.h>
#include <stdint.h>

#define NROW 16384
#define KC 64
#define NCHUNK (NROW / KC)            /* 256 */
#define STAGE_B 32768u                /* A 16KB fp16 + B 16KB fp16 */
#define BIGH_SMEM (4 * 32768)         /* 131072 */
#define PREP_SMEM ((64 * 64 + 128 * 132) * 4)

__device__ __half g_TtH[(size_t)128 * NROW];          /* B operand, K-major fp16 */
__device__ __half g_adjH[(size_t)NROW * NROW];        /* fp16 copy of adj (512MB) */
__device__ float  g_X[(size_t)NROW * 128];            /* layer activations fp32  */

__device__ __forceinline__ float eluf(float x) { return x > 0.f ? x : expm1f(x); }
__device__ __forceinline__ uint32_t swz(uint32_t x) { return x ^ ((x >> 3) & 0x70); }

__device__ __forceinline__ uint32_t smem_u32(const void* p) {
    uint32_t a;
    asm("{ .reg .u64 t; cvta.to.shared.u64 t, %1; cvt.u32.u64 %0, t; }" : "=r"(a) : "l"(p));
    return a;
}
__device__ __forceinline__ void cp_async16(uint32_t dst, const void* src) {
    asm volatile("cp.async.cg.shared.global [%0], [%1], 16;" :: "r"(dst), "l"(src) : "memory");
}
__device__ __forceinline__ void ldsm_x4(uint32_t* r, uint32_t addr) {
    asm volatile("ldmatrix.sync.aligned.m8n8.x4.shared.b16 {%0,%1,%2,%3}, [%4];"
                 : "=r"(r[0]), "=r"(r[1]), "=r"(r[2]), "=r"(r[3]) : "r"(addr));
}
__device__ __forceinline__ void mma_f16(float* c, const uint32_t* a, const uint32_t* b) {
    asm volatile(
        "mma.sync.aligned.m16n8k16.row.col.f32.f16.f16.f32 "
        "{%0,%1,%2,%3}, {%4,%5,%6,%7}, {%8,%9}, {%0,%1,%2,%3};"
        : "+f"(c[0]), "+f"(c[1]), "+f"(c[2]), "+f"(c[3])
        : "r"(a[0]), "r"(a[1]), "r"(a[2]), "r"(a[3]), "r"(b[0]), "r"(b[1]));
}
/* pack (lo, hi) -> f16x2 reg */
__device__ __forceinline__ uint32_t f16x2(float hi, float lo) {
    uint32_t h;
    asm("cvt.rn.f16x2.f32 %0, %1, %2;" : "=r"(h) : "f"(hi), "f"(lo));
    return h;
}

/* TtH[j][k] = fp16( sum_d f(src[k][d(+64)]) * W[d][j&63] ) */
__global__ __launch_bounds__(512) void gcn_prep(const float* __restrict__ Xin,
                                                const float* __restrict__ W,
                                                int apply_elu, int use_gx) {
    extern __shared__ float sm[];
    float* sW = sm;
    float* sXT = sm + 64 * 64;
    const float* src = use_gx ? (const float*)g_X : Xin;
    int tid = threadIdx.x;
    int k0 = blockIdx.x * 128;

    for (int l = tid; l < 64 * 64; l += 512) sW[l] = W[l];
    #pragma unroll
    for (int it = 0; it < 32; ++it) {
        int l = it * 512 + tid;
        int k = l >> 7, d = l & 127;
        float v = src[(size_t)(k0 + k) * 128 + d];
        if (apply_elu) v = eluf(v);
        sXT[d * 132 + k] = v;
    }
    __syncthreads();

    int warp = tid >> 5, lane = tid & 31;
    int k = lane * 4;
    for (int jp = warp; jp < 64; jp += 16) {
        float4 a0 = make_float4(0.f, 0.f, 0.f, 0.f);
        float4 a1 = make_float4(0.f, 0.f, 0.f, 0.f);
        #pragma unroll 16
        for (int d = 0; d < 64; ++d) {
            float w = sW[d * 64 + jp];
            float4 xs = *(const float4*)&sXT[d * 132 + k];
            float4 xu = *(const float4*)&sXT[(64 + d) * 132 + k];
            a0.x = fmaf(xs.x, w, a0.x); a0.y = fmaf(xs.y, w, a0.y);
            a0.z = fmaf(xs.z, w, a0.z); a0.w = fmaf(xs.w, w, a0.w);
            a1.x = fmaf(xu.x, w, a1.x); a1.y = fmaf(xu.y, w, a1.y);
            a1.z = fmaf(xu.z, w, a1.z); a1.w = fmaf(xu.w, w, a1.w);
        }
        uint2 p0 = make_uint2(f16x2(a0.y, a0.x), f16x2(a0.w, a0.z));
        uint2 p1 = make_uint2(f16x2(a1.y, a1.x), f16x2(a1.w, a1.z));
        *(uint2*)&g_TtH[(size_t)jp * NROW + k0 + k] = p0;
        *(uint2*)&g_TtH[(size_t)(jp + 64) * NROW + k0 + k] = p1;
    }
}

/* g_X[m][n] = elu( sum_k adj[m][k] * Tt[n][k] + bias[n&63] ), fp16 m16n8k16.
   MODE 0: A streamed fp32 from adj, converted in-kernel, fp16 copy written to g_adjH.
   MODE 1: A cp.async'd fp16 from g_adjH. */
template<int MODE>
__global__ __launch_bounds__(256, 1) void gcn_big_h(const float* __restrict__ adj,
                                                    const float* __restrict__ bias) {
    extern __shared__ char dsm[];
    uint32_t sb = smem_u32(dsm);
    int tid = threadIdx.x;
    int lane = tid & 31, wid = tid >> 5;
    int wm = wid & 3, wn = wid >> 2;      /* warp tile: 32(m) x 64(n) */
    int m0 = blockIdx.x * 128;
    int q = lane >> 3, li = lane & 7;

    float acc[2][8][4];
    #pragma unroll
    for (int i = 0; i < 2; ++i)
        #pragma unroll
        for (int j = 0; j < 8; ++j)
            #pragma unroll
            for (int r = 0; r < 4; ++r) acc[i][j][r] = 0.f;

    /* fragment base offsets (k-step t applied via ^ (t*32)) */
    uint32_t aB[2], bB[4];
    #pragma unroll
    for (int mi = 0; mi < 2; ++mi)
        aB[mi] = swz((uint32_t)((wm * 32 + mi * 16 + (q & 1) * 8 + li) * 128 + (q >> 1) * 16));
    #pragma unroll
    for (int pp = 0; pp < 4; ++pp)
        bB[pp] = swz((uint32_t)((wn * 64 + (pp * 2 + (q >> 1)) * 8 + li) * 128 + (q & 1) * 16));

#define CPB(ii) do {                                                            \
    uint32_t st_ = sb + (uint32_t)((ii) & 3) * STAGE_B + 16384u;                \
    int k0_ = (ii) * KC;                                                        \
    _Pragma("unroll")                                                           \
    for (int j_ = 0; j_ < 4; ++j_) {                                            \
        int v_ = j_ * 256 + tid;                                                \
        int br_ = v_ >> 3, bs_ = v_ & 7;                                        \
        cp_async16(st_ + swz((uint32_t)(br_ * 128 + bs_ * 16)),                 \
                   g_TtH + (size_t)br_ * NROW + k0_ + bs_ * 8);                 \
    }                                                                           \
} while (0)

#define CPA(ii) do {                                                            \
    uint32_t st_ = sb + (uint32_t)((ii) & 3) * STAGE_B;                         \
    int k0_ = (ii) * KC;                                                        \
    _Pragma("unroll")                                                           \
    for (int j_ = 0; j_ < 4; ++j_) {                                            \
        int v_ = j_ * 256 + tid;                                                \
        int ar_ = v_ >> 3, as_ = v_ & 7;                                        \
        cp_async16(st_ + swz((uint32_t)(ar_ * 128 + as_ * 16)),                 \
                   g_adjH + (size_t)(m0 + ar_) * NROW + k0_ + as_ * 8);         \
    }                                                                           \
} while (0)

#define LDGS(buf, ii) do {                                                      \
    int k0_ = (ii) * KC;                                                        \
    _Pragma("unroll")                                                           \
    for (int j_ = 0; j_ < 8; ++j_) {                                            \
        int v_ = j_ * 256 + tid;                                                \
        int ar_ = v_ >> 4, as_ = v_ & 15;                                       \
        buf[j_] = *(const float4*)&adj[(size_t)(m0 + ar_) * NROW + k0_ + as_ * 4]; \
    }                                                                           \
} while (0)

#define STSA(buf, ii) do {                                                      \
    uint32_t st_ = sb + (uint32_t)((ii) & 3) * STAGE_B;                         \
    int k0_ = (ii) * KC;                                                        \
    _Pragma("unroll")                                                           \
    for (int j_ = 0; j_ < 8; ++j_) {                                            \
        int v_ = j_ * 256 + tid;                                                \
        int ar_ = v_ >> 4, as_ = v_ & 15;                                       \
        uint32_t h0_ = f16x2(buf[j_].y, buf[j_].x);                             \
        uint32_t h1_ = f16x2(buf[j_].w, buf[j_].z);                             \
        uint32_t so_ = st_ + swz((uint32_t)(ar_ * 128 + as_ * 8));              \
        asm volatile("st.shared.v2.b32 [%0], {%1,%2};" :: "r"(so_), "r"(h0_), "r"(h1_)); \
        *(uint2*)&g_adjH[(size_t)(m0 + ar_) * NROW + k0_ + as_ * 4] = make_uint2(h0_, h1_); \
    }                                                                           \
} while (0)

    float4 rbuf[2][8];
    if (MODE == 0) {
        LDGS(rbuf[0], 0);
        STSA(rbuf[0], 0);
        LDGS(rbuf[1], 1);
        CPB(0); asm volatile("cp.async.commit_group;" ::: "memory");
        CPB(1); asm volatile("cp.async.commit_group;" ::: "memory");
        CPB(2); asm volatile("cp.async.commit_group;" ::: "memory");
    } else {
        CPA(0); CPB(0); asm volatile("cp.async.commit_group;" ::: "memory");
        CPA(1); CPB(1); asm volatile("cp.async.commit_group;" ::: "memory");
        CPA(2); CPB(2); asm volatile("cp.async.commit_group;" ::: "memory");
    }

    #pragma unroll 1
    for (int i = 0; i < NCHUNK; ++i) {
        asm volatile("cp.async.wait_group 2;" ::: "memory");
        __syncthreads();
        if (MODE == 0) {
            if (i + 1 < NCHUNK) STSA(rbuf[(i + 1) & 1], i + 1);
            if (i + 2 < NCHUNK) LDGS(rbuf[i & 1], i + 2);
            if (i + 3 < NCHUNK) CPB(i + 3);
        } else {
            if (i + 3 < NCHUNK) { CPA(i + 3); CPB(i + 3); }
        }
        asm volatile("cp.async.commit_group;" ::: "memory");

        uint32_t sA = sb + (uint32_t)(i & 3) * STAGE_B;
        uint32_t sB = sA + 16384u;
        #pragma unroll
        for (int t = 0; t < 4; ++t) {
            uint32_t ax = (uint32_t)(t * 32);
            uint32_t af[2][4], bq[4][4];
            ldsm_x4(af[0], sA + (aB[0] ^ ax));
            ldsm_x4(af[1], sA + (aB[1] ^ ax));
            #pragma unroll
            for (int pp = 0; pp < 4; ++pp)
                ldsm_x4(bq[pp], sB + (bB[pp] ^ ax));
            #pragma unroll
            for (int mi = 0; mi < 2; ++mi)
                #pragma unroll
                for (int pp = 0; pp < 4; ++pp) {
                    mma_f16(acc[mi][2 * pp],     af[mi], &bq[pp][0]);
                    mma_f16(acc[mi][2 * pp + 1], af[mi], &bq[pp][2]);
                }
        }
    }
    asm volatile("cp.async.wait_group 0;" ::: "memory");

    /* epilogue: bias + elu, fragment-direct float2 stores */
    int col0 = wn * 64 + (lane & 3) * 2;
    int rbase = m0 + wm * 32 + (lane >> 2);
    #pragma unroll
    for (int mi = 0; mi < 2; ++mi)
        #pragma unroll
        for (int ni = 0; ni < 8; ++ni) {
            int col = col0 + ni * 8;
            float b0v = bias[col & 63], b1v = bias[(col + 1) & 63];
            int rlo = rbase + mi * 16;
            float2 v0 = make_float2(eluf(acc[mi][ni][0] + b0v), eluf(acc[mi][ni][1] + b1v));
            float2 v1 = make_float2(eluf(acc[mi][ni][2] + b0v), eluf(acc[mi][ni][3] + b1v));
            *(float2*)&g_X[(size_t)rlo * 128 + col] = v0;
            *(float2*)&g_X[(size_t)(rlo + 8) * 128 + col] = v1;
        }
#undef CPB
#undef CPA
#undef LDGS
#undef STSA
}

/* out[k][o] = sum_j g_X[k][j] * Wl[o][j] + bl[o] */
__global__ __launch_bounds__(256) void gcn_final(const float* __restrict__ Wl,
                                                 const float* __restrict__ bl,
                                                 float* __restrict__ out) {
    __shared__ float sWlT[128 * 32];
    int tid = threadIdx.x;
    for (int l = tid; l < 4096; l += 256) {
        int o = l >> 7, j = l & 127;
        sWlT[j * 32 + o] = Wl[l];
    }
    __syncthreads();
    int warp = tid >> 5, lane = tid & 31;
    int k0 = blockIdx.x * 128;
    float b = bl[lane];
    for (int r = warp; r < 128; r += 8) {
        const float* yrow = g_X + (size_t)(k0 + r) * 128;
        float acc = b;
        #pragma unroll 16
        for (int j = 0; j < 128; ++j)
            acc = fmaf(__ldg(&yrow[j]), sWlT[j * 32 + lane], acc);
        out[(size_t)(k0 + r) * 32 + lane] = acc;
    }
}

extern "C" void kernel_launch(void* const* d_in, const int* in_sizes, int n_in,
                              void* d_out, int out_size) {
    const float* z   = (const float*)d_in[0];
    const float* adj = (const float*)d_in[1];
    const float* W0  = (const float*)d_in[2];
    const float* b0  = (const float*)d_in[3];
    const float* W1  = (const float*)d_in[4];
    const float* b1  = (const float*)d_in[5];
    const float* Wl  = (const float*)d_in[6];
    const float* bl  = (const float*)d_in[7];
    float* out = (float*)d_out;

    cudaFuncSetAttribute(gcn_prep, cudaFuncAttributeMaxDynamicSharedMemorySize, PREP_SMEM);
    cudaFuncSetAttribute(gcn_big_h<0>, cudaFuncAttributeMaxDynamicSharedMemorySize, BIGH_SMEM);
    cudaFuncSetAttribute(gcn_big_h<1>, cudaFuncAttributeMaxDynamicSharedMemorySize, BIGH_SMEM);

    gcn_prep<<<128, 512, PREP_SMEM>>>(z, W0, 1, 0);
    gcn_big_h<0><<<128, 256, BIGH_SMEM>>>(adj, b0);
    gcn_prep<<<128, 512, PREP_SMEM>>>(z, W1, 0, 1);
    gcn_big_h<1><<<128, 256, BIGH_SMEM>>>(adj, b1);
    gcn_final<<<128, 256>>>(Wl, bl, out);
}

// round 8
// speedup vs baseline: 1.2746x; 1.1596x over previous
#include <cuda_runtime.h>
#include <cuda_fp16.h>
#include <stdint.h>

#define NROW 16384
#define KC 64
#define NCHUNK (NROW / KC)            /* 256 */
#define STAGE_B 32768u                /* A 16KB fp16 + B 16KB fp16 */
#define BIGH_SMEM (4 * 32768)         /* 131072 */
#define PREP_SMEM ((64 * 64 + 128 * 132) * 4)

__device__ __half g_TtH[(size_t)128 * NROW];          /* B operand, K-major fp16 */
__device__ __half g_adjH[(size_t)NROW * NROW];        /* fp16 copy of adj (512MB) */
__device__ float  g_X[(size_t)NROW * 128];            /* layer activations fp32  */

__device__ __forceinline__ float eluf(float x) { return x > 0.f ? x : expm1f(x); }
__device__ __forceinline__ uint32_t swz(uint32_t x) { return x ^ ((x >> 3) & 0x70); }

__device__ __forceinline__ uint32_t smem_u32(const void* p) {
    uint32_t a;
    asm("{ .reg .u64 t; cvta.to.shared.u64 t, %1; cvt.u32.u64 %0, t; }" : "=r"(a) : "l"(p));
    return a;
}
__device__ __forceinline__ void cp_async16(uint32_t dst, const void* src) {
    asm volatile("cp.async.cg.shared.global [%0], [%1], 16;" :: "r"(dst), "l"(src) : "memory");
}
__device__ __forceinline__ void ldsm_x4(uint32_t* r, uint32_t addr) {
    asm volatile("ldmatrix.sync.aligned.m8n8.x4.shared.b16 {%0,%1,%2,%3}, [%4];"
                 : "=r"(r[0]), "=r"(r[1]), "=r"(r[2]), "=r"(r[3]) : "r"(addr));
}
__device__ __forceinline__ void mma_f16(float* c, const uint32_t* a, const uint32_t* b) {
    asm volatile(
        "mma.sync.aligned.m16n8k16.row.col.f32.f16.f16.f32 "
        "{%0,%1,%2,%3}, {%4,%5,%6,%7}, {%8,%9}, {%0,%1,%2,%3};"
        : "+f"(c[0]), "+f"(c[1]), "+f"(c[2]), "+f"(c[3])
        : "r"(a[0]), "r"(a[1]), "r"(a[2]), "r"(a[3]), "r"(b[0]), "r"(b[1]));
}
__device__ __forceinline__ uint32_t f16x2(float hi, float lo) {
    uint32_t h;
    asm("cvt.rn.f16x2.f32 %0, %1, %2;" : "=r"(h) : "f"(hi), "f"(lo));
    return h;
}

/* pure-stream fp32 -> fp16 conversion of adj (1GB read, 512MB write) */
__global__ __launch_bounds__(256) void cvt_adj(const float* __restrict__ adj) {
    size_t n4 = (size_t)NROW * NROW / 4;                 /* float4 count */
    size_t stride = (size_t)gridDim.x * 256;
    for (size_t i = (size_t)blockIdx.x * 256 + threadIdx.x; i < n4; i += stride) {
        float4 v = *(const float4*)(adj + i * 4);
        uint2 h = make_uint2(f16x2(v.y, v.x), f16x2(v.w, v.z));
        *(uint2*)&g_adjH[i * 4] = h;
    }
}

/* TtH[j][k] = fp16( sum_d f(src[k][d(+64)]) * W[d][j&63] ) */
__global__ __launch_bounds__(512) void gcn_prep(const float* __restrict__ Xin,
                                                const float* __restrict__ W,
                                                int apply_elu, int use_gx) {
    extern __shared__ float sm[];
    float* sW = sm;
    float* sXT = sm + 64 * 64;
    const float* src = use_gx ? (const float*)g_X : Xin;
    int tid = threadIdx.x;
    int k0 = blockIdx.x * 128;

    for (int l = tid; l < 64 * 64; l += 512) sW[l] = W[l];
    #pragma unroll
    for (int it = 0; it < 32; ++it) {
        int l = it * 512 + tid;
        int k = l >> 7, d = l & 127;
        float v = src[(size_t)(k0 + k) * 128 + d];
        if (apply_elu) v = eluf(v);
        sXT[d * 132 + k] = v;
    }
    __syncthreads();

    int warp = tid >> 5, lane = tid & 31;
    int k = lane * 4;
    for (int jp = warp; jp < 64; jp += 16) {
        float4 a0 = make_float4(0.f, 0.f, 0.f, 0.f);
        float4 a1 = make_float4(0.f, 0.f, 0.f, 0.f);
        #pragma unroll 16
        for (int d = 0; d < 64; ++d) {
            float w = sW[d * 64 + jp];
            float4 xs = *(const float4*)&sXT[d * 132 + k];
            float4 xu = *(const float4*)&sXT[(64 + d) * 132 + k];
            a0.x = fmaf(xs.x, w, a0.x); a0.y = fmaf(xs.y, w, a0.y);
            a0.z = fmaf(xs.z, w, a0.z); a0.w = fmaf(xs.w, w, a0.w);
            a1.x = fmaf(xu.x, w, a1.x); a1.y = fmaf(xu.y, w, a1.y);
            a1.z = fmaf(xu.z, w, a1.z); a1.w = fmaf(xu.w, w, a1.w);
        }
        uint2 p0 = make_uint2(f16x2(a0.y, a0.x), f16x2(a0.w, a0.z));
        uint2 p1 = make_uint2(f16x2(a1.y, a1.x), f16x2(a1.w, a1.z));
        *(uint2*)&g_TtH[(size_t)jp * NROW + k0 + k] = p0;
        *(uint2*)&g_TtH[(size_t)(jp + 64) * NROW + k0 + k] = p1;
    }
}

/* g_X[m][n] = elu( sum_k adjH[m][k] * TtH[n][k] + bias[n&63] ), fp16 m16n8k16 */
__global__ __launch_bounds__(256, 1) void gcn_bigh(const float* __restrict__ bias) {
    extern __shared__ char dsm[];
    uint32_t sb = smem_u32(dsm);
    int tid = threadIdx.x;
    int lane = tid & 31, wid = tid >> 5;
    int wm = wid & 3, wn = wid >> 2;      /* warp tile: 32(m) x 64(n) */
    int m0 = blockIdx.x * 128;
    int q = lane >> 3, li = lane & 7;

    float acc[2][8][4];
    #pragma unroll
    for (int i = 0; i < 2; ++i)
        #pragma unroll
        for (int j = 0; j < 8; ++j)
            #pragma unroll
            for (int r = 0; r < 4; ++r) acc[i][j][r] = 0.f;

    uint32_t aB[2], bB[4];
    #pragma unroll
    for (int mi = 0; mi < 2; ++mi)
        aB[mi] = swz((uint32_t)((wm * 32 + mi * 16 + (q & 1) * 8 + li) * 128 + (q >> 1) * 16));
    #pragma unroll
    for (int pp = 0; pp < 4; ++pp)
        bB[pp] = swz((uint32_t)((wn * 64 + (pp * 2 + (q >> 1)) * 8 + li) * 128 + (q & 1) * 16));

#define CPAB(ii) do {                                                           \
    uint32_t stA_ = sb + (uint32_t)((ii) & 3) * STAGE_B;                        \
    uint32_t stB_ = stA_ + 16384u;                                              \
    int k0_ = (ii) * KC;                                                        \
    _Pragma("unroll")                                                           \
    for (int j_ = 0; j_ < 4; ++j_) {                                            \
        int v_ = j_ * 256 + tid;                                                \
        int r_ = v_ >> 3, s_ = v_ & 7;                                          \
        uint32_t o_ = swz((uint32_t)(r_ * 128 + s_ * 16));                      \
        cp_async16(stA_ + o_, g_adjH + (size_t)(m0 + r_) * NROW + k0_ + s_ * 8);\
        cp_async16(stB_ + o_, g_TtH + (size_t)r_ * NROW + k0_ + s_ * 8);        \
    }                                                                           \
    asm volatile("cp.async.commit_group;" ::: "memory");                        \
} while (0)

    CPAB(0); CPAB(1); CPAB(2);

    #pragma unroll 1
    for (int i = 0; i < NCHUNK; ++i) {
        asm volatile("cp.async.wait_group 2;" ::: "memory");
        __syncthreads();
        if (i + 3 < NCHUNK) CPAB(i + 3);
        else asm volatile("cp.async.commit_group;" ::: "memory");

        uint32_t sA = sb + (uint32_t)(i & 3) * STAGE_B;
        uint32_t sB = sA + 16384u;
        #pragma unroll
        for (int t = 0; t < 4; ++t) {
            uint32_t ax = (uint32_t)(t * 32);
            uint32_t af[2][4], bq[4][4];
            ldsm_x4(af[0], sA + (aB[0] ^ ax));
            ldsm_x4(af[1], sA + (aB[1] ^ ax));
            #pragma unroll
            for (int pp = 0; pp < 4; ++pp)
                ldsm_x4(bq[pp], sB + (bB[pp] ^ ax));
            #pragma unroll
            for (int mi = 0; mi < 2; ++mi)
                #pragma unroll
                for (int pp = 0; pp < 4; ++pp) {
                    mma_f16(acc[mi][2 * pp],     af[mi], &bq[pp][0]);
                    mma_f16(acc[mi][2 * pp + 1], af[mi], &bq[pp][2]);
                }
        }
    }
    asm volatile("cp.async.wait_group 0;" ::: "memory");

    int col0 = wn * 64 + (lane & 3) * 2;
    int rbase = m0 + wm * 32 + (lane >> 2);
    #pragma unroll
    for (int mi = 0; mi < 2; ++mi)
        #pragma unroll
        for (int ni = 0; ni < 8; ++ni) {
            int col = col0 + ni * 8;
            float b0v = bias[col & 63], b1v = bias[(col + 1) & 63];
            int rlo = rbase + mi * 16;
            float2 v0 = make_float2(eluf(acc[mi][ni][0] + b0v), eluf(acc[mi][ni][1] + b1v));
            float2 v1 = make_float2(eluf(acc[mi][ni][2] + b0v), eluf(acc[mi][ni][3] + b1v));
            *(float2*)&g_X[(size_t)rlo * 128 + col] = v0;
            *(float2*)&g_X[(size_t)(rlo + 8) * 128 + col] = v1;
        }
#undef CPAB
}

/* out[k][o] = sum_j g_X[k][j] * Wl[o][j] + bl[o] */
__global__ __launch_bounds__(256) void gcn_final(const float* __restrict__ Wl,
                                                 const float* __restrict__ bl,
                                                 float* __restrict__ out) {
    __shared__ float sWlT[128 * 32];
    int tid = threadIdx.x;
    for (int l = tid; l < 4096; l += 256) {
        int o = l >> 7, j = l & 127;
        sWlT[j * 32 + o] = Wl[l];
    }
    __syncthreads();
    int warp = tid >> 5, lane = tid & 31;
    int k0 = blockIdx.x * 128;
    float b = bl[lane];
    for (int r = warp; r < 128; r += 8) {
        const float* yrow = g_X + (size_t)(k0 + r) * 128;
        float acc = b;
        #pragma unroll 16
        for (int j = 0; j < 128; ++j)
            acc = fmaf(__ldg(&yrow[j]), sWlT[j * 32 + lane], acc);
        out[(size_t)(k0 + r) * 32 + lane] = acc;
    }
}

extern "C" void kernel_launch(void* const* d_in, const int* in_sizes, int n_in,
                              void* d_out, int out_size) {
    const float* z   = (const float*)d_in[0];
    const float* adj = (const float*)d_in[1];
    const float* W0  = (const float*)d_in[2];
    const float* b0  = (const float*)d_in[3];
    const float* W1  = (const float*)d_in[4];
    const float* b1  = (const float*)d_in[5];
    const float* Wl  = (const float*)d_in[6];
    const float* bl  = (const float*)d_in[7];
    float* out = (float*)d_out;

    cudaFuncSetAttribute(gcn_prep, cudaFuncAttributeMaxDynamicSharedMemorySize, PREP_SMEM);
    cudaFuncSetAttribute(gcn_bigh, cudaFuncAttributeMaxDynamicSharedMemorySize, BIGH_SMEM);

    cvt_adj<<<16384, 256>>>(adj);
    gcn_prep<<<128, 512, PREP_SMEM>>>(z, W0, 1, 0);
    gcn_bigh<<<128, 256, BIGH_SMEM>>>(b0);
    gcn_prep<<<128, 512, PREP_SMEM>>>(z, W1, 0, 1);
    gcn_bigh<<<128, 256, BIGH_SMEM>>>(b1);
    gcn_final<<<128, 256>>>(Wl, bl, out);
}